// round 1
// baseline (speedup 1.0000x reference)
#include <cuda_runtime.h>

// TransposeTDLayer: y[b, k + 2*l, o] += sum_i W[k,l,o,i] * x[b,l,i]; y += bias.
// Shapes: x (64,512,128) f32; W (8,512,128,128) f32; bias (1030,128) f32;
//         y (64,1030,128) f32.
// Gather form: for output position p, contributing (k,l) satisfy k = p - 2l in [0,8),
// i.e. k has parity of p and l = (p-k)/2 — at most 4 pairs. No atomics needed.

#define BATCH  64
#define LIN    512
#define CIN    128
#define COUT   128
#define KSZ    8
#define STRD   2
#define OUTP   1030

__global__ __launch_bounds__(256, 4)
void tdconv_gather_kernel(const float* __restrict__ x,
                          const float* __restrict__ w,
                          const float* __restrict__ bias,
                          float* __restrict__ y)
{
    const int p = blockIdx.x;          // output position 0..1029

    __shared__ float Xs[BATCH][33];    // [b][ci-chunk], pad 33: conflict-free
    __shared__ float Ws[COUT][33];     // [o][ci-chunk]

    const int tid = threadIdx.x;
    const int to  = tid & 15;          // o-group: o = to + 16*j, j=0..7
    const int tb  = tid >> 4;          // b-group: b = 4*tb + i, i=0..3

    // accumulators init with bias (same across batch)
    float acc[4][8];
    #pragma unroll
    for (int j = 0; j < 8; j++) {
        float bb = bias[p * COUT + to + 16 * j];
        #pragma unroll
        for (int i = 0; i < 4; i++) acc[i][j] = bb;
    }

    const int par = p & 1;
    for (int kk = par; kk < KSZ; kk += 2) {
        const int l2 = p - kk;
        if (l2 < 0 || l2 >= STRD * LIN) continue;
        const int l = l2 >> 1;
        const float* __restrict__ wl = w + ((size_t)(kk * LIN + l) * COUT) * CIN;

        for (int cb = 0; cb < CIN; cb += 32) {
            __syncthreads();   // protect prior reads before overwrite

            // ---- load X chunk: 64 rows x 32 ci = 512 float4 ----
            #pragma unroll
            for (int t = 0; t < 2; t++) {
                int idx = tid + t * 256;
                int b   = idx >> 3;
                int c4  = (idx & 7) * 4;
                float4 v = *(const float4*)(x + ((size_t)b * LIN + l) * CIN + cb + c4);
                Xs[b][c4 + 0] = v.x;
                Xs[b][c4 + 1] = v.y;
                Xs[b][c4 + 2] = v.z;
                Xs[b][c4 + 3] = v.w;
            }
            // ---- load W chunk: 128 rows x 32 ci = 1024 float4 ----
            #pragma unroll
            for (int t = 0; t < 4; t++) {
                int idx = tid + t * 256;
                int o   = idx >> 3;
                int c4  = (idx & 7) * 4;
                float4 v = *(const float4*)(wl + (size_t)o * CIN + cb + c4);
                Ws[o][c4 + 0] = v.x;
                Ws[o][c4 + 1] = v.y;
                Ws[o][c4 + 2] = v.z;
                Ws[o][c4 + 3] = v.w;
            }
            __syncthreads();

            // ---- compute: 32 ci steps, 4b x 8o outer product each ----
            #pragma unroll 8
            for (int ci = 0; ci < 32; ci++) {
                float xr[4], wr[8];
                #pragma unroll
                for (int i = 0; i < 4; i++) xr[i] = Xs[4 * tb + i][ci];
                #pragma unroll
                for (int j = 0; j < 8; j++) wr[j] = Ws[to + 16 * j][ci];
                #pragma unroll
                for (int i = 0; i < 4; i++)
                    #pragma unroll
                    for (int j = 0; j < 8; j++)
                        acc[i][j] = fmaf(xr[i], wr[j], acc[i][j]);
            }
        }
    }

    // ---- store: each thread 4b x 8o ----
    #pragma unroll
    for (int i = 0; i < 4; i++) {
        const int b = 4 * tb + i;
        float* __restrict__ yp = y + ((size_t)b * OUTP + p) * COUT;
        #pragma unroll
        for (int j = 0; j < 8; j++)
            yp[to + 16 * j] = acc[i][j];
    }
}

extern "C" void kernel_launch(void* const* d_in, const int* in_sizes, int n_in,
                              void* d_out, int out_size)
{
    const float* x    = (const float*)d_in[0];  // (64,512,128)
    const float* w    = (const float*)d_in[1];  // (8,512,128,128)
    const float* bias = (const float*)d_in[2];  // (1030,128)
    float* y = (float*)d_out;                   // (64,1030,128)

    tdconv_gather_kernel<<<OUTP, 256>>>(x, w, bias, y);
}

// round 3
// speedup vs baseline: 1.3648x; 1.3648x over previous
#include <cuda_runtime.h>
#include <cuda_bf16.h>
#include <cstdint>

// TransposeTDLayer via warp-level mma.sync bf16-split GEMM (sm_103-base legal).
// y[b, p, o] = bias[p,o] + sum_{(k,l): k+2l=p} sum_ci W[k,l,o,ci] * x[b,l,ci]
// Per p: D[o=128, b=64] = sum_j A_j[128x128] * B_j[64x128]^T, K-major both.
// fp32 split into bf16 hi + lo; 3 MMAs per k-step (hh, hl, lh).

#define BATCH 64
#define LIN   512
#define CIN   128
#define COUT  128
#define KSZ   8
#define OUTP  1030

static __device__ __forceinline__ void mma_bf16(
    float* c, const uint32_t* a, const uint32_t* b)
{
    asm volatile(
        "mma.sync.aligned.m16n8k16.row.col.f32.bf16.bf16.f32 "
        "{%0,%1,%2,%3}, {%4,%5,%6,%7}, {%8,%9}, {%0,%1,%2,%3};"
        : "+f"(c[0]), "+f"(c[1]), "+f"(c[2]), "+f"(c[3])
        : "r"(a[0]), "r"(a[1]), "r"(a[2]), "r"(a[3]), "r"(b[0]), "r"(b[1]));
}

// float2 -> packed bf16x2 (hi) and packed bf16x2 (residual lo)
static __device__ __forceinline__ void split2(float2 v, uint32_t& hi, uint32_t& lo)
{
    __nv_bfloat162 h = __floats2bfloat162_rn(v.x, v.y);
    hi = *reinterpret_cast<uint32_t*>(&h);
    float rx = v.x - __bfloat162float(h.x);
    float ry = v.y - __bfloat162float(h.y);
    __nv_bfloat162 l = __floats2bfloat162_rn(rx, ry);
    lo = *reinterpret_cast<uint32_t*>(&l);
}

__global__ void __launch_bounds__(256)
tdconv_mma_kernel(const float* __restrict__ x,
                  const float* __restrict__ w,
                  const float* __restrict__ bias,
                  float* __restrict__ y)
{
    const int p    = blockIdx.x;
    const int tid  = threadIdx.x;
    const int wid  = tid >> 5;
    const int lane = tid & 31;
    const int g    = lane >> 2;    // group id 0..7
    const int t    = lane & 3;     // thread-in-group 0..3

    const int mrow = (wid >> 1) * 32;   // cout base for this warp (0,32,64,96)
    const int ncol = (wid & 1) * 32;    // batch base for this warp (0,32)

    // contributing (k,l): k = par + 2j, l = m - j, j in [j0, j1]
    const int par = p & 1;
    const int m   = (p - par) >> 1;
    int j0 = m - (LIN - 1); if (j0 < 0) j0 = 0;
    int j1 = m < 3 ? m : 3;
    const int nblk = j1 - j0 + 1;

    // accumulators initialized with bias (same for all batch columns)
    float acc[2][4][4];
    #pragma unroll
    for (int mi = 0; mi < 2; mi++) {
        const float b_g  = bias[p * COUT + mrow + mi * 16 + g];
        const float b_g8 = bias[p * COUT + mrow + mi * 16 + g + 8];
        #pragma unroll
        for (int ni = 0; ni < 4; ni++) {
            acc[mi][ni][0] = b_g;  acc[mi][ni][1] = 0.f;
            acc[mi][ni][2] = b_g8; acc[mi][ni][3] = 0.f;
        }
    }
    // note: c1/c3 (odd batch cols) also need bias; fix: bias is per (p,o), same
    // for every batch col, so c1 = b_g, c3 = b_g8 too.
    #pragma unroll
    for (int mi = 0; mi < 2; mi++)
        #pragma unroll
        for (int ni = 0; ni < 4; ni++) {
            acc[mi][ni][1] = acc[mi][ni][0];
            acc[mi][ni][3] = acc[mi][ni][2];
        }

    for (int i = 0; i < nblk; i++) {
        const int j = j0 + i;
        const int l = m - j;
        const int k = par + 2 * j;

        const float* __restrict__ wp = w + (size_t)(k * LIN + l) * (COUT * CIN);
        // A base for this lane: row (mrow+g), col 2t
        const float* __restrict__ wa = wp + (size_t)(mrow + g) * CIN + 2 * t;
        // B base: batch row (ncol+g), position l, col 2t
        const float* __restrict__ xb = x + ((size_t)(ncol + g) * LIN + l) * CIN + 2 * t;

        #pragma unroll 2
        for (int ks = 0; ks < 8; ks++) {
            const int k0 = ks * 16;

            // ---- load A fragments (2 m-tiles x 4 float2) ----
            float2 av[2][4];
            #pragma unroll
            for (int mi = 0; mi < 2; mi++) {
                const float* base = wa + (size_t)mi * 16 * CIN + k0;
                av[mi][0] = *(const float2*)(base);
                av[mi][1] = *(const float2*)(base + 8 * CIN);
                av[mi][2] = *(const float2*)(base + 8);
                av[mi][3] = *(const float2*)(base + 8 * CIN + 8);
            }
            // ---- load B fragments (4 n-tiles x 2 float2) ----
            float2 bv[4][2];
            #pragma unroll
            for (int ni = 0; ni < 4; ni++) {
                const float* base = xb + (size_t)ni * 8 * LIN * CIN + k0;
                bv[ni][0] = *(const float2*)(base);
                bv[ni][1] = *(const float2*)(base + 8);
            }

            // ---- split to bf16 hi/lo ----
            uint32_t ahi[2][4], alo[2][4], bhi[4][2], blo[4][2];
            #pragma unroll
            for (int mi = 0; mi < 2; mi++)
                #pragma unroll
                for (int q = 0; q < 4; q++)
                    split2(av[mi][q], ahi[mi][q], alo[mi][q]);
            #pragma unroll
            for (int ni = 0; ni < 4; ni++)
                #pragma unroll
                for (int q = 0; q < 2; q++)
                    split2(bv[ni][q], bhi[ni][q], blo[ni][q]);

            // ---- mma: hh, hl, lh ----
            #pragma unroll
            for (int mi = 0; mi < 2; mi++)
                #pragma unroll
                for (int ni = 0; ni < 4; ni++) {
                    mma_bf16(acc[mi][ni], ahi[mi], bhi[ni]);
                    mma_bf16(acc[mi][ni], ahi[mi], blo[ni]);
                    mma_bf16(acc[mi][ni], alo[mi], bhi[ni]);
                }
        }
    }

    // ---- store: D[o, b] -> y[b, p, o] ----
    #pragma unroll
    for (int mi = 0; mi < 2; mi++) {
        const int o0 = mrow + mi * 16 + g;
        const int o8 = o0 + 8;
        #pragma unroll
        for (int ni = 0; ni < 4; ni++) {
            const int b0 = ncol + ni * 8 + 2 * t;
            float* y0 = y + ((size_t)b0 * OUTP + p) * COUT;
            float* y1 = y0 + (size_t)OUTP * COUT;   // b0 + 1
            y0[o0] = acc[mi][ni][0];
            y1[o0] = acc[mi][ni][1];
            y0[o8] = acc[mi][ni][2];
            y1[o8] = acc[mi][ni][3];
        }
    }
}

extern "C" void kernel_launch(void* const* d_in, const int* in_sizes, int n_in,
                              void* d_out, int out_size)
{
    const float* x    = (const float*)d_in[0];  // (64,512,128)
    const float* w    = (const float*)d_in[1];  // (8,512,128,128)
    const float* bias = (const float*)d_in[2];  // (1030,128)
    float* y = (float*)d_out;                   // (64,1030,128)

    tdconv_mma_kernel<<<OUTP, 256>>>(x, w, bias, y);
}

// round 4
// speedup vs baseline: 1.7267x; 1.2651x over previous
#include <cuda_runtime.h>
#include <cuda_bf16.h>
#include <cstdint>

// TransposeTDLayer via smem-staged bf16-split mma.sync GEMM.
// y[b,p,o] = bias[p,o] + sum_{(k,l):k+2l=p} sum_ci W[k,l,o,ci] * x[b,l,ci]
// Per p: D[128 x 64] = sum_j A_j[128x128] B_j[64x128]^T, both K-major.
// fp32 -> bf16 hi + residual lo (split once, stored in smem); 3 MMAs hh,hl,lh.

#define BATCH 64
#define LIN   512
#define CIN   128
#define COUT  128
#define OUTP  1030

// bf16 tile row stride: 128 bf16 + 8 pad = 136 el = 272 B (68 words -> 4-bank
// rotation per row => conflict-free LDSM and 2-way-max STS)
#define RSTRIDE 272
#define AHI_OFF 0
#define ALO_OFF 34816                 // 128*272
#define BHI_OFF 69632
#define BLO_OFF 87040                 // + 64*272
#define BUF_BYTES 104448
#define SMEM_TOTAL (2 * BUF_BYTES)    // 208896

static __device__ __forceinline__ uint32_t smem_u32(const void* p) {
    uint32_t a;
    asm("{ .reg .u64 t; cvta.to.shared.u64 t, %1; cvt.u32.u64 %0, t; }"
        : "=r"(a) : "l"(p));
    return a;
}

static __device__ __forceinline__ void mma_bf16(
    float* c, const uint32_t* a, const uint32_t* b)
{
    asm volatile(
        "mma.sync.aligned.m16n8k16.row.col.f32.bf16.bf16.f32 "
        "{%0,%1,%2,%3}, {%4,%5,%6,%7}, {%8,%9}, {%0,%1,%2,%3};"
        : "+f"(c[0]), "+f"(c[1]), "+f"(c[2]), "+f"(c[3])
        : "r"(a[0]), "r"(a[1]), "r"(a[2]), "r"(a[3]), "r"(b[0]), "r"(b[1]));
}

static __device__ __forceinline__ void ldsm_x4(uint32_t* r, uint32_t addr) {
    asm volatile("ldmatrix.sync.aligned.m8n8.x4.shared.b16 {%0,%1,%2,%3}, [%4];"
                 : "=r"(r[0]), "=r"(r[1]), "=r"(r[2]), "=r"(r[3]) : "r"(addr));
}

// split float4 -> two packed bf16x2 (hi) + two packed bf16x2 (residual lo),
// store as 8B each to padded tile
static __device__ __forceinline__ void split_store4(
    uint32_t hi_addr, uint32_t lo_addr, float4 v)
{
    __nv_bfloat162 h0 = __floats2bfloat162_rn(v.x, v.y);
    __nv_bfloat162 h1 = __floats2bfloat162_rn(v.z, v.w);
    float rx = v.x - __bfloat162float(h0.x);
    float ry = v.y - __bfloat162float(h0.y);
    float rz = v.z - __bfloat162float(h1.x);
    float rw = v.w - __bfloat162float(h1.y);
    __nv_bfloat162 l0 = __floats2bfloat162_rn(rx, ry);
    __nv_bfloat162 l1 = __floats2bfloat162_rn(rz, rw);
    uint32_t uh0 = *reinterpret_cast<uint32_t*>(&h0);
    uint32_t uh1 = *reinterpret_cast<uint32_t*>(&h1);
    uint32_t ul0 = *reinterpret_cast<uint32_t*>(&l0);
    uint32_t ul1 = *reinterpret_cast<uint32_t*>(&l1);
    asm volatile("st.shared.v2.b32 [%0], {%1,%2};" :: "r"(hi_addr), "r"(uh0), "r"(uh1));
    asm volatile("st.shared.v2.b32 [%0], {%1,%2};" :: "r"(lo_addr), "r"(ul0), "r"(ul1));
}

__global__ void __launch_bounds__(256, 1)
tdconv_mma2_kernel(const float* __restrict__ x,
                   const float* __restrict__ w,
                   const float* __restrict__ bias,
                   float* __restrict__ y)
{
    extern __shared__ char smem[];
    const uint32_t sbase = smem_u32(smem);

    const int p    = blockIdx.x;
    const int tid  = threadIdx.x;
    const int wid  = tid >> 5;
    const int lane = tid & 31;
    const int g    = lane >> 2;     // 0..7
    const int t    = lane & 3;      // 0..3
    const int lr   = lane & 7;
    const int grp  = lane >> 3;     // 0..3

    const int mrow = (wid >> 1) * 32;   // cout base (0,32,64,96)
    const int ncol = (wid & 1) * 32;    // batch base (0,32)

    // contributing blocks
    const int par = p & 1;
    const int m   = (p - par) >> 1;
    int j0 = m - (LIN - 1); if (j0 < 0) j0 = 0;
    int j1 = m < 3 ? m : 3;
    const int nblk = j1 - j0 + 1;

    // ldmatrix lane offsets within a tile (bytes)
    // A: matrices (m0-7,k0-7),(m8-15,k0-7),(m0-7,k8-15),(m8-15,k8-15)
    const uint32_t a_loff = (uint32_t)(mrow + lr + (grp & 1) * 8) * RSTRIDE
                          + (uint32_t)(grp >> 1) * 16;
    // B: matrices (n0-7,k0-7),(n0-7,k8-15),(n8-15,k0-7),(n8-15,k8-15)
    const uint32_t b_loff = (uint32_t)(ncol + lr + (grp >> 1) * 8) * RSTRIDE
                          + (uint32_t)(grp & 1) * 16;

    // accumulators init with bias (same across batch cols)
    float acc[2][4][4];
    #pragma unroll
    for (int mi = 0; mi < 2; mi++) {
        const float b_g  = bias[p * COUT + mrow + mi * 16 + g];
        const float b_g8 = bias[p * COUT + mrow + mi * 16 + g + 8];
        #pragma unroll
        for (int ni = 0; ni < 4; ni++) {
            acc[mi][ni][0] = b_g;  acc[mi][ni][1] = b_g;
            acc[mi][ni][2] = b_g8; acc[mi][ni][3] = b_g8;
        }
    }

    // ---- prologue: load + convert + store block 0 ----
    {
        const int j = j0, l = m - j, k = par + 2 * j;
        const float* __restrict__ wp = w + (size_t)(k * LIN + l) * (COUT * CIN);
        const uint32_t buf = sbase;
        #pragma unroll
        for (int it = 0; it < 16; it++) {
            int idx = tid + it * 256;
            float4 v = reinterpret_cast<const float4*>(wp)[idx];
            uint32_t off = (uint32_t)(idx >> 5) * RSTRIDE + (uint32_t)(idx & 31) * 8;
            split_store4(buf + AHI_OFF + off, buf + ALO_OFF + off, v);
        }
        #pragma unroll
        for (int it = 0; it < 8; it++) {
            int idx = tid + it * 256;
            int b   = idx >> 5;
            float4 v = *reinterpret_cast<const float4*>(
                x + ((size_t)b * LIN + l) * CIN + (size_t)(idx & 31) * 4);
            uint32_t off = (uint32_t)b * RSTRIDE + (uint32_t)(idx & 31) * 8;
            split_store4(buf + BHI_OFF + off, buf + BLO_OFF + off, v);
        }
    }
    __syncthreads();

    for (int i = 0; i < nblk; i++) {
        // ---- issue next block's global loads (hide DRAM under MMA) ----
        float4 wr[16], xr[8];
        const bool has_next = (i + 1 < nblk);
        if (has_next) {
            const int j = j0 + i + 1, l = m - j, k = par + 2 * j;
            const float* __restrict__ wp = w + (size_t)(k * LIN + l) * (COUT * CIN);
            #pragma unroll
            for (int it = 0; it < 16; it++)
                wr[it] = reinterpret_cast<const float4*>(wp)[tid + it * 256];
            #pragma unroll
            for (int it = 0; it < 8; it++) {
                int idx = tid + it * 256;
                xr[it] = *reinterpret_cast<const float4*>(
                    x + ((size_t)(idx >> 5) * LIN + l) * CIN + (size_t)(idx & 31) * 4);
            }
        }

        // ---- MMA over current buffer ----
        const uint32_t buf = sbase + (uint32_t)(i & 1) * BUF_BYTES;
        const uint32_t ah_base = buf + AHI_OFF + a_loff;
        const uint32_t al_base = buf + ALO_OFF + a_loff;
        const uint32_t bh_base = buf + BHI_OFF + b_loff;
        const uint32_t bl_base = buf + BLO_OFF + b_loff;

        #pragma unroll 2
        for (int ks = 0; ks < 8; ks++) {
            const uint32_t koff = (uint32_t)ks * 32;
            uint32_t ahi[2][4], alo[2][4], bh[2][4], bl[2][4];
            #pragma unroll
            for (int mi = 0; mi < 2; mi++) {
                ldsm_x4(ahi[mi], ah_base + (uint32_t)mi * (16 * RSTRIDE) + koff);
                ldsm_x4(alo[mi], al_base + (uint32_t)mi * (16 * RSTRIDE) + koff);
            }
            #pragma unroll
            for (int pr = 0; pr < 2; pr++) {
                ldsm_x4(bh[pr], bh_base + (uint32_t)pr * (16 * RSTRIDE) + koff);
                ldsm_x4(bl[pr], bl_base + (uint32_t)pr * (16 * RSTRIDE) + koff);
            }
            #pragma unroll
            for (int mi = 0; mi < 2; mi++)
                #pragma unroll
                for (int ni = 0; ni < 4; ni++) {
                    const uint32_t* bhp = &bh[ni >> 1][(ni & 1) * 2];
                    const uint32_t* blp = &bl[ni >> 1][(ni & 1) * 2];
                    mma_bf16(acc[mi][ni], ahi[mi], bhp);
                    mma_bf16(acc[mi][ni], ahi[mi], blp);
                    mma_bf16(acc[mi][ni], alo[mi], bhp);
                }
        }

        // ---- convert + store next block into the other buffer ----
        if (has_next) {
            const uint32_t nbuf = sbase + (uint32_t)((i + 1) & 1) * BUF_BYTES;
            #pragma unroll
            for (int it = 0; it < 16; it++) {
                int idx = tid + it * 256;
                uint32_t off = (uint32_t)(idx >> 5) * RSTRIDE + (uint32_t)(idx & 31) * 8;
                split_store4(nbuf + AHI_OFF + off, nbuf + ALO_OFF + off, wr[it]);
            }
            #pragma unroll
            for (int it = 0; it < 8; it++) {
                int idx = tid + it * 256;
                uint32_t off = (uint32_t)(idx >> 5) * RSTRIDE + (uint32_t)(idx & 31) * 8;
                split_store4(nbuf + BHI_OFF + off, nbuf + BLO_OFF + off, xr[it]);
            }
        }
        __syncthreads();
    }

    // ---- epilogue: D[o,b] -> y[b,p,o] ----
    #pragma unroll
    for (int mi = 0; mi < 2; mi++) {
        const int o0 = mrow + mi * 16 + g;
        const int o8 = o0 + 8;
        #pragma unroll
        for (int ni = 0; ni < 4; ni++) {
            const int b0 = ncol + ni * 8 + 2 * t;
            float* y0 = y + ((size_t)b0 * OUTP + p) * COUT;
            float* y1 = y0 + (size_t)OUTP * COUT;
            y0[o0] = acc[mi][ni][0];
            y1[o0] = acc[mi][ni][1];
            y0[o8] = acc[mi][ni][2];
            y1[o8] = acc[mi][ni][3];
        }
    }
}

extern "C" void kernel_launch(void* const* d_in, const int* in_sizes, int n_in,
                              void* d_out, int out_size)
{
    const float* x    = (const float*)d_in[0];  // (64,512,128)
    const float* w    = (const float*)d_in[1];  // (8,512,128,128)
    const float* bias = (const float*)d_in[2];  // (1030,128)
    float* y = (float*)d_out;                   // (64,1030,128)

    static bool configured = false;
    if (!configured) {
        cudaFuncSetAttribute(tdconv_mma2_kernel,
                             cudaFuncAttributeMaxDynamicSharedMemorySize, SMEM_TOTAL);
        configured = true;
    }
    tdconv_mma2_kernel<<<OUTP, 256, SMEM_TOTAL>>>(x, w, bias, y);
}